// round 12
// baseline (speedup 1.0000x reference)
#include <cuda_runtime.h>
#include <math.h>

#define N_NODES 32768
#define DMODEL  512
#define NHEADS  8
#define HDIM    64
#define LN_EPS  1e-5f

// 64 MB scratch for attn [N, D] (device-global: allocation rules forbid cudaMalloc)
__device__ float g_attn[N_NODES * DMODEL];

// ---------------------------------------------------------------------------
// Kernel 1: Y = act(h @ W)  for W in {Wq, Wk, Wv} selected by blockIdx.z.
// Tiled SGEMM: BM=64, BN=64, BK=16, 256 threads, 4x4 register tile per thread.
// ---------------------------------------------------------------------------
__global__ __launch_bounds__(256, 4)
void qkv_kernel(const float* __restrict__ h,
                const float* __restrict__ Wq,
                const float* __restrict__ Wk,
                const float* __restrict__ Wv,
                float* __restrict__ qo,
                float* __restrict__ ko,
                float* __restrict__ vo)
{
    __shared__ float As[16][65];   // A^T tile, padded: conflict-free both ways
    __shared__ float Bs[16][64];

    const int z = blockIdx.z;
    const float* W  = (z == 0) ? Wq : (z == 1) ? Wk : Wv;
    float* out      = (z == 0) ? qo : (z == 1) ? ko : vo;
    const bool relu = (z < 2);

    const int tid  = threadIdx.x;
    const int tx   = tid & 15;      // col group (4 cols each)
    const int ty   = tid >> 4;      // row group (4 rows each)
    const int row0 = blockIdx.y * 64;
    const int col0 = blockIdx.x * 64;

    // global-load indices
    const int lrow = tid >> 2;      // 0..63
    const int lseg = tid & 3;       // 0..3  (4 floats each)
    const int bkr  = tid >> 4;      // 0..15
    const int bseg = tid & 15;      // 0..15 (4 floats each)

    float acc[4][4];
#pragma unroll
    for (int i = 0; i < 4; i++)
#pragma unroll
        for (int j = 0; j < 4; j++) acc[i][j] = 0.f;

    for (int k0 = 0; k0 < DMODEL; k0 += 16) {
        // load A tile (64x16) transposed into As[k][m]
        float4 av = *(const float4*)&h[(long)(row0 + lrow) * DMODEL + k0 + lseg * 4];
        As[lseg * 4 + 0][lrow] = av.x;
        As[lseg * 4 + 1][lrow] = av.y;
        As[lseg * 4 + 2][lrow] = av.z;
        As[lseg * 4 + 3][lrow] = av.w;
        // load B tile (16x64)
        *(float4*)&Bs[bkr][bseg * 4] =
            *(const float4*)&W[(long)(k0 + bkr) * DMODEL + col0 + bseg * 4];
        __syncthreads();

#pragma unroll
        for (int kk = 0; kk < 16; kk++) {
            float a0 = As[kk][ty * 4 + 0];
            float a1 = As[kk][ty * 4 + 1];
            float a2 = As[kk][ty * 4 + 2];
            float a3 = As[kk][ty * 4 + 3];
            float4 b = *(float4*)&Bs[kk][tx * 4];
            acc[0][0] += a0 * b.x; acc[0][1] += a0 * b.y; acc[0][2] += a0 * b.z; acc[0][3] += a0 * b.w;
            acc[1][0] += a1 * b.x; acc[1][1] += a1 * b.y; acc[1][2] += a1 * b.z; acc[1][3] += a1 * b.w;
            acc[2][0] += a2 * b.x; acc[2][1] += a2 * b.y; acc[2][2] += a2 * b.z; acc[2][3] += a2 * b.w;
            acc[3][0] += a3 * b.x; acc[3][1] += a3 * b.y; acc[3][2] += a3 * b.z; acc[3][3] += a3 * b.w;
        }
        __syncthreads();
    }

#pragma unroll
    for (int i = 0; i < 4; i++) {
        int r = row0 + ty * 4 + i;
        float4 o;
        o.x = acc[i][0]; o.y = acc[i][1]; o.z = acc[i][2]; o.w = acc[i][3];
        if (relu) {
            o.x = fmaxf(o.x, 0.f); o.y = fmaxf(o.y, 0.f);
            o.z = fmaxf(o.z, 0.f); o.w = fmaxf(o.w, 0.f);
        }
        *(float4*)&out[(long)r * DMODEL + col0 + tx * 4] = o;
    }
}

// ---------------------------------------------------------------------------
// Kernel 2: per-node linear attention.
//   kv = sum_h k[h]^T v[h]   (64x64), num = q @ kv, denom = q @ ksum,
//   attn = num / denom.  One block (64 threads) per node; thread e owns
//   column e of kv in registers.
// ---------------------------------------------------------------------------
__global__ __launch_bounds__(64, 8)
void attn_kernel(const float* __restrict__ q,
                 const float* __restrict__ k,
                 const float* __restrict__ v)
{
    __shared__ float sq[NHEADS * HDIM];
    __shared__ float sk[NHEADS * HDIM];
    __shared__ float sv[NHEADS * HDIM];
    __shared__ float spart[NHEADS * HDIM];
    __shared__ float sden[NHEADS];

    const int b   = blockIdx.x;
    const int tid = threadIdx.x;          // = column / d index (0..63)
    const long base = (long)b * DMODEL;

#pragma unroll
    for (int j = 0; j < 8; j++) {
        int i = tid + j * 64;
        sq[i] = q[base + i];
        sk[i] = k[base + i];
        sv[i] = v[base + i];
    }
    __syncthreads();

    // ksum[d] for d = tid, and denom partials q[h][d]*ksum[d]
    float ksum_d = 0.f;
#pragma unroll
    for (int hh = 0; hh < NHEADS; hh++) ksum_d += sk[hh * HDIM + tid];
#pragma unroll
    for (int hh = 0; hh < NHEADS; hh++)
        spart[hh * HDIM + tid] = sq[hh * HDIM + tid] * ksum_d;

    // kv column e = tid
    float kv[HDIM];
#pragma unroll
    for (int d = 0; d < HDIM; d++) kv[d] = 0.f;
#pragma unroll
    for (int hh = 0; hh < NHEADS; hh++) {
        float v_he = sv[hh * HDIM + tid];
#pragma unroll
        for (int d = 0; d < HDIM; d++)
            kv[d] += sk[hh * HDIM + d] * v_he;
    }

    // num[h][e]
    float numr[NHEADS];
#pragma unroll
    for (int hh = 0; hh < NHEADS; hh++) {
        float s = 0.f;
#pragma unroll
        for (int d = 0; d < HDIM; d++)
            s += sq[hh * HDIM + d] * kv[d];
        numr[hh] = s;
    }
    __syncthreads();

    if (tid < NHEADS) {
        float s = 0.f;
#pragma unroll
        for (int d = 0; d < HDIM; d++) s += spart[tid * HDIM + d];
        sden[tid] = s;
    }
    __syncthreads();

#pragma unroll
    for (int hh = 0; hh < NHEADS; hh++)
        g_attn[base + hh * HDIM + tid] = numr[hh] / sden[hh];
}

// ---------------------------------------------------------------------------
// Kernel 3: fh = attn @ Wf; out = LayerNorm(h + fh) * gamma + beta.
// BM=32 rows per block x full 512 cols, 256 threads.
// Thread layout: rg = tid>>5 (4 rows each), cg = tid&31 (16 cols each).
// Each warp (fixed rg) owns 4 COMPLETE rows -> warp-shuffle LayerNorm.
// ---------------------------------------------------------------------------
__global__ __launch_bounds__(256, 2)
void out_kernel(const float* __restrict__ hin,
                const float* __restrict__ Wf,
                const float* __restrict__ gamma,
                const float* __restrict__ beta,
                float* __restrict__ out)
{
    __shared__ float As[8][33];
    __shared__ float Bs[8][512];

    const int tid = threadIdx.x;
    const int cg  = tid & 31;    // 16 cols: [cg*16, cg*16+16)
    const int rg  = tid >> 5;    // 4 rows: [rg*4, rg*4+4)
    const int r0  = blockIdx.x * 32;

    float acc[4][16];
#pragma unroll
    for (int i = 0; i < 4; i++)
#pragma unroll
        for (int c = 0; c < 16; c++) acc[i][c] = 0.f;

    const int arow = tid >> 3;   // 0..31
    const int akk  = tid & 7;    // 0..7

    for (int k0 = 0; k0 < DMODEL; k0 += 8) {
        As[akk][arow] = g_attn[(long)(r0 + arow) * DMODEL + k0 + akk];
#pragma unroll
        for (int j = 0; j < 4; j++) {
            int idx = tid + j * 256;          // 0..1023
            int kk  = idx >> 7;               // 0..7
            int seg = idx & 127;              // 0..127
            *(float4*)&Bs[kk][seg * 4] =
                *(const float4*)&Wf[(long)(k0 + kk) * DMODEL + seg * 4];
        }
        __syncthreads();

#pragma unroll
        for (int kk = 0; kk < 8; kk++) {
            float a[4];
#pragma unroll
            for (int i = 0; i < 4; i++) a[i] = As[kk][rg * 4 + i];
#pragma unroll
            for (int j = 0; j < 4; j++) {
                float4 bv = *(float4*)&Bs[kk][cg * 16 + j * 4];
#pragma unroll
                for (int i = 0; i < 4; i++) {
                    acc[i][j * 4 + 0] += a[i] * bv.x;
                    acc[i][j * 4 + 1] += a[i] * bv.y;
                    acc[i][j * 4 + 2] += a[i] * bv.z;
                    acc[i][j * 4 + 3] += a[i] * bv.w;
                }
            }
        }
        __syncthreads();
    }

    // epilogue: residual + LayerNorm, warp-local (warp rg owns rows rg*4..+3)
    const int colbase = cg * 16;
#pragma unroll
    for (int i = 0; i < 4; i++) {
        const int r = r0 + rg * 4 + i;
        float x[16];
#pragma unroll
        for (int j = 0; j < 4; j++) {
            float4 hv = *(const float4*)&hin[(long)r * DMODEL + colbase + j * 4];
            x[j * 4 + 0] = acc[i][j * 4 + 0] + hv.x;
            x[j * 4 + 1] = acc[i][j * 4 + 1] + hv.y;
            x[j * 4 + 2] = acc[i][j * 4 + 2] + hv.z;
            x[j * 4 + 3] = acc[i][j * 4 + 3] + hv.w;
        }
        float s = 0.f;
#pragma unroll
        for (int c = 0; c < 16; c++) s += x[c];
#pragma unroll
        for (int o = 16; o > 0; o >>= 1) s += __shfl_xor_sync(0xffffffffu, s, o);
        const float mean = s * (1.0f / DMODEL);

        float vs = 0.f;
#pragma unroll
        for (int c = 0; c < 16; c++) {
            float d = x[c] - mean;
            vs += d * d;
        }
#pragma unroll
        for (int o = 16; o > 0; o >>= 1) vs += __shfl_xor_sync(0xffffffffu, vs, o);
        const float rstd = rsqrtf(vs * (1.0f / DMODEL) + LN_EPS);

#pragma unroll
        for (int j = 0; j < 4; j++) {
            float4 gv = *(const float4*)&gamma[colbase + j * 4];
            float4 bv = *(const float4*)&beta[colbase + j * 4];
            float4 o4;
            o4.x = (x[j * 4 + 0] - mean) * rstd * gv.x + bv.x;
            o4.y = (x[j * 4 + 1] - mean) * rstd * gv.y + bv.y;
            o4.z = (x[j * 4 + 2] - mean) * rstd * gv.z + bv.z;
            o4.w = (x[j * 4 + 3] - mean) * rstd * gv.w + bv.w;
            *(float4*)&out[(long)r * DMODEL + colbase + j * 4] = o4;
        }
    }
}

// ---------------------------------------------------------------------------
// Launch: inputs per metadata order: h, Wq, Wk, Wv, Wf, ln_gamma, ln_beta.
// Output tuple (out, q, k, v) flattened: [N*D | N*D | N*D | N*D].
// ---------------------------------------------------------------------------
extern "C" void kernel_launch(void* const* d_in, const int* in_sizes, int n_in,
                              void* d_out, int out_size)
{
    const float* h     = (const float*)d_in[0];
    const float* Wq    = (const float*)d_in[1];
    const float* Wk    = (const float*)d_in[2];
    const float* Wv    = (const float*)d_in[3];
    const float* Wf    = (const float*)d_in[4];
    const float* gamma = (const float*)d_in[5];
    const float* beta  = (const float*)d_in[6];

    float* out = (float*)d_out;
    float* q   = out + (long)N_NODES * DMODEL;
    float* k   = out + 2L * N_NODES * DMODEL;
    float* v   = out + 3L * N_NODES * DMODEL;

    dim3 g1(DMODEL / 64, N_NODES / 64, 3);
    qkv_kernel<<<g1, 256>>>(h, Wq, Wk, Wv, q, k, v);

    attn_kernel<<<N_NODES, 64>>>(q, k, v);

    out_kernel<<<N_NODES / 32, 256>>>(h, Wf, gamma, beta, out);
}

// round 13
// speedup vs baseline: 1.5331x; 1.5331x over previous
#include <cuda_runtime.h>
#include <math.h>

#define N_NODES 32768
#define DMODEL  512
#define NHEADS  8
#define HDIM    64
#define LN_EPS  1e-5f

// 64 MB scratch for attn [N, D] (device-global: allocation rules forbid cudaMalloc)
__device__ float g_attn[N_NODES * DMODEL];

// ---------------------------------------------------------------------------
// GEMM: C[M,512] = act(A[M,512] @ B[512,512]) (+ resid), M = 32768.
// BM=128, BN=128, BK=8, 256 threads, 8x8 register tile, double-buffered smem.
// ---------------------------------------------------------------------------
template<bool RELU, bool RESID>
__global__ __launch_bounds__(256, 2)
void gemm128(const float* __restrict__ A,
             const float* __restrict__ B,
             const float* __restrict__ resid,
             float* __restrict__ C)
{
    // As stride 132: conflict-free transposed STS, still 16B-aligned (132%4==0)
    __shared__ float As[2][8][132];
    __shared__ float Bs[2][8][128];

    const int tid  = threadIdx.x;
    const int tx   = tid & 15;          // 8 cols each
    const int ty   = tid >> 4;          // 8 rows each
    const int row0 = blockIdx.y * 128;
    const int col0 = blockIdx.x * 128;

    // global-load mapping
    const int arow = tid >> 1;          // 0..127
    const int aseg = tid & 1;           // 0..1  (float4)
    const int brow = tid >> 5;          // 0..7
    const int bseg = tid & 31;          // 0..31 (float4)

    const float* Ag = A + (long)(row0 + arow) * DMODEL + aseg * 4;
    const float* Bg = B + (long)brow * DMODEL + col0 + bseg * 4;

    float acc[8][8];
#pragma unroll
    for (int i = 0; i < 8; i++)
#pragma unroll
        for (int j = 0; j < 8; j++) acc[i][j] = 0.f;

    // preload k0 = 0 into buffer 0
    {
        float4 av = *(const float4*)Ag;
        float4 bv = *(const float4*)Bg;
        As[0][aseg * 4 + 0][arow] = av.x;
        As[0][aseg * 4 + 1][arow] = av.y;
        As[0][aseg * 4 + 2][arow] = av.z;
        As[0][aseg * 4 + 3][arow] = av.w;
        *(float4*)&Bs[0][brow][bseg * 4] = bv;
    }
    __syncthreads();

    int buf = 0;
    for (int k0 = 0; k0 < DMODEL; k0 += 8) {
        float4 av2, bv2;
        const bool more = (k0 + 8) < DMODEL;
        if (more) {
            av2 = *(const float4*)(Ag + k0 + 8);
            bv2 = *(const float4*)(Bg + (long)(k0 + 8) * DMODEL);
        }

#pragma unroll
        for (int kk = 0; kk < 8; kk++) {
            float a[8], b[8];
            *(float4*)&a[0] = *(float4*)&As[buf][kk][ty * 8];
            *(float4*)&a[4] = *(float4*)&As[buf][kk][ty * 8 + 4];
            *(float4*)&b[0] = *(float4*)&Bs[buf][kk][tx * 8];
            *(float4*)&b[4] = *(float4*)&Bs[buf][kk][tx * 8 + 4];
#pragma unroll
            for (int i = 0; i < 8; i++)
#pragma unroll
                for (int j = 0; j < 8; j++)
                    acc[i][j] += a[i] * b[j];
        }

        if (more) {
            const int nb = buf ^ 1;
            As[nb][aseg * 4 + 0][arow] = av2.x;
            As[nb][aseg * 4 + 1][arow] = av2.y;
            As[nb][aseg * 4 + 2][arow] = av2.z;
            As[nb][aseg * 4 + 3][arow] = av2.w;
            *(float4*)&Bs[nb][brow][bseg * 4] = bv2;
        }
        __syncthreads();
        buf ^= 1;
    }

#pragma unroll
    for (int i = 0; i < 8; i++) {
        const long r = row0 + ty * 8 + i;
#pragma unroll
        for (int jj = 0; jj < 2; jj++) {
            float4 o;
            o.x = acc[i][jj * 4 + 0];
            o.y = acc[i][jj * 4 + 1];
            o.z = acc[i][jj * 4 + 2];
            o.w = acc[i][jj * 4 + 3];
            if (RESID) {
                float4 hv = *(const float4*)&resid[r * DMODEL + col0 + tx * 8 + jj * 4];
                o.x += hv.x; o.y += hv.y; o.z += hv.z; o.w += hv.w;
            }
            if (RELU) {
                o.x = fmaxf(o.x, 0.f); o.y = fmaxf(o.y, 0.f);
                o.z = fmaxf(o.z, 0.f); o.w = fmaxf(o.w, 0.f);
            }
            *(float4*)&C[r * DMODEL + col0 + tx * 8 + jj * 4] = o;
        }
    }
}

// ---------------------------------------------------------------------------
// Per-node linear attention (unchanged from passing R12 kernel).
// ---------------------------------------------------------------------------
__global__ __launch_bounds__(64, 8)
void attn_kernel(const float* __restrict__ q,
                 const float* __restrict__ k,
                 const float* __restrict__ v)
{
    __shared__ float sq[NHEADS * HDIM];
    __shared__ float sk[NHEADS * HDIM];
    __shared__ float sv[NHEADS * HDIM];
    __shared__ float spart[NHEADS * HDIM];
    __shared__ float sden[NHEADS];

    const int b   = blockIdx.x;
    const int tid = threadIdx.x;          // column / d index (0..63)
    const long base = (long)b * DMODEL;

#pragma unroll
    for (int j = 0; j < 8; j++) {
        int i = tid + j * 64;
        sq[i] = q[base + i];
        sk[i] = k[base + i];
        sv[i] = v[base + i];
    }
    __syncthreads();

    float ksum_d = 0.f;
#pragma unroll
    for (int hh = 0; hh < NHEADS; hh++) ksum_d += sk[hh * HDIM + tid];
#pragma unroll
    for (int hh = 0; hh < NHEADS; hh++)
        spart[hh * HDIM + tid] = sq[hh * HDIM + tid] * ksum_d;

    float kv[HDIM];
#pragma unroll
    for (int d = 0; d < HDIM; d++) kv[d] = 0.f;
#pragma unroll
    for (int hh = 0; hh < NHEADS; hh++) {
        float v_he = sv[hh * HDIM + tid];
#pragma unroll
        for (int d = 0; d < HDIM; d++)
            kv[d] += sk[hh * HDIM + d] * v_he;
    }

    float numr[NHEADS];
#pragma unroll
    for (int hh = 0; hh < NHEADS; hh++) {
        float s = 0.f;
#pragma unroll
        for (int d = 0; d < HDIM; d++)
            s += sq[hh * HDIM + d] * kv[d];
        numr[hh] = s;
    }
    __syncthreads();

    if (tid < NHEADS) {
        float s = 0.f;
#pragma unroll
        for (int d = 0; d < HDIM; d++) s += spart[tid * HDIM + d];
        sden[tid] = s;
    }
    __syncthreads();

#pragma unroll
    for (int hh = 0; hh < NHEADS; hh++)
        g_attn[base + hh * HDIM + tid] = numr[hh] / sden[hh];
}

// ---------------------------------------------------------------------------
// In-place LayerNorm over out[N,512]: one warp per row, 16 floats per lane.
// ---------------------------------------------------------------------------
__global__ __launch_bounds__(256, 8)
void ln_kernel(float* __restrict__ out,
               const float* __restrict__ gamma,
               const float* __restrict__ beta)
{
    const int warp = threadIdx.x >> 5;
    const int lane = threadIdx.x & 31;
    const long row = (long)blockIdx.x * 8 + warp;
    float* p = out + row * DMODEL;

    float4 x[4];
#pragma unroll
    for (int j = 0; j < 4; j++)
        x[j] = *(const float4*)&p[(j * 32 + lane) * 4];

    float s = 0.f;
#pragma unroll
    for (int j = 0; j < 4; j++) s += x[j].x + x[j].y + x[j].z + x[j].w;
#pragma unroll
    for (int o = 16; o > 0; o >>= 1) s += __shfl_xor_sync(0xffffffffu, s, o);
    const float mean = s * (1.0f / DMODEL);

    float vs = 0.f;
#pragma unroll
    for (int j = 0; j < 4; j++) {
        float dx = x[j].x - mean; vs += dx * dx;
        dx = x[j].y - mean; vs += dx * dx;
        dx = x[j].z - mean; vs += dx * dx;
        dx = x[j].w - mean; vs += dx * dx;
    }
#pragma unroll
    for (int o = 16; o > 0; o >>= 1) vs += __shfl_xor_sync(0xffffffffu, vs, o);
    const float rstd = rsqrtf(vs * (1.0f / DMODEL) + LN_EPS);

#pragma unroll
    for (int j = 0; j < 4; j++) {
        const int c = (j * 32 + lane) * 4;
        float4 gv = *(const float4*)&gamma[c];
        float4 bv = *(const float4*)&beta[c];
        float4 o4;
        o4.x = (x[j].x - mean) * rstd * gv.x + bv.x;
        o4.y = (x[j].y - mean) * rstd * gv.y + bv.y;
        o4.z = (x[j].z - mean) * rstd * gv.z + bv.z;
        o4.w = (x[j].w - mean) * rstd * gv.w + bv.w;
        *(float4*)&p[c] = o4;
    }
}

// ---------------------------------------------------------------------------
// Launch. Inputs: h, Wq, Wk, Wv, Wf, ln_gamma, ln_beta.
// Output tuple (out, q, k, v): [N*D | N*D | N*D | N*D].
// ---------------------------------------------------------------------------
extern "C" void kernel_launch(void* const* d_in, const int* in_sizes, int n_in,
                              void* d_out, int out_size)
{
    const float* h     = (const float*)d_in[0];
    const float* Wq    = (const float*)d_in[1];
    const float* Wk    = (const float*)d_in[2];
    const float* Wv    = (const float*)d_in[3];
    const float* Wf    = (const float*)d_in[4];
    const float* gamma = (const float*)d_in[5];
    const float* beta  = (const float*)d_in[6];

    float* out = (float*)d_out;
    float* q   = out + (long)N_NODES * DMODEL;
    float* k   = out + 2L * N_NODES * DMODEL;
    float* v   = out + 3L * N_NODES * DMODEL;

    float* attn_ptr = nullptr;
    cudaGetSymbolAddress((void**)&attn_ptr, g_attn);

    dim3 gg(DMODEL / 128, N_NODES / 128);   // (4, 256)

    gemm128<true,  false><<<gg, 256>>>(h, Wq, nullptr, q);
    gemm128<true,  false><<<gg, 256>>>(h, Wk, nullptr, k);
    gemm128<false, false><<<gg, 256>>>(h, Wv, nullptr, v);

    attn_kernel<<<N_NODES, 64>>>(q, k, v);

    gemm128<false, true><<<gg, 256>>>(attn_ptr, Wf, h, out);

    ln_kernel<<<N_NODES / 8, 256>>>(out, gamma, beta);
}